// round 14
// baseline (speedup 1.0000x reference)
#include <cuda_runtime.h>
#include <math.h>

#define BATCH 512
#define MMEM  2000
#define FDIM  2304
#define NS_RED 64
#define GSPLIT 8

// ---------------- scratch (device globals: allocation-free) ----------------
__device__ float g_bufA[512*16*49*49];
__device__ float g_bufB[512*32*25*25];
__device__ float g_bufC[512*64*13*13];
__device__ float g_t4  [512*2304];
__device__ float g_z   [512*2304];
__device__ float g_zhat[512*2304];
__device__ float g_w   [512*2000];
__device__ float g_zn  [512];
__device__ float g_mn  [2000];
__device__ float g_part[64*NS_RED*2];
__device__ float g_sc  [64];
__device__ float g_bi  [64];
__device__ float g_gpart[GSPLIT*512*2304];

__device__ __forceinline__ void fma4(float4& a, float4 w, float v) {
    a.x = fmaf(v, w.x, a.x); a.y = fmaf(v, w.y, a.y);
    a.z = fmaf(v, w.z, a.z); a.w = fmaf(v, w.w, a.w);
}

// ======= direct conv, ALL shapes compile-time, incremented pointers ========
template<int CI, int K, int S, int PXY, int CO, int IH, int IW, int OH, int OW,
         int P, bool PRE, int EPI>
__global__ __launch_bounds__(256, 3) void convd(
    const float* __restrict__ in, const float* __restrict__ wgt,
    const float* __restrict__ cbias,
    const float* __restrict__ sc, const float* __restrict__ bi,
    float* __restrict__ out)
{
    constexpr int GY = (OH + PXY - 1) / PXY;
    constexpr int TOTAL = BATCH * GY * OW;
    constexpr int IHW = IH * IW;
    constexpr int OHW = OH * OW;

    __shared__ float wsm[K*K*CI*16];
    __shared__ float scs[CI], bis[CI];
    const int tid = threadIdx.x;
    const int co0 = blockIdx.y * 16;

    constexpr int WN = K*K*CI*16;
    for (int idx = tid; idx < WN; idx += 256) {
        int j = idx & 15, r = idx >> 4;
        int ci = r % CI; r /= CI;
        int kx = r % K, ky = r / K;
        wsm[idx] = wgt[(((co0 + j)*CI + ci)*K + ky)*K + kx];
    }
    if (PRE) for (int c = tid; c < CI; c += 256) { scs[c] = sc[c]; bis[c] = bi[c]; }
    __syncthreads();

    int p = blockIdx.x * 256 + tid;
    if (p >= TOTAL) return;
    const int ox = p % OW; int t = p / OW;
    const int gy = t % GY;
    const int n  = t / GY;
    const int oy0 = gy * PXY;

    float4 acc[PXY][4];
#pragma unroll
    for (int i = 0; i < PXY; i++)
#pragma unroll
        for (int q = 0; q < 4; q++) acc[i][q] = make_float4(0.f,0.f,0.f,0.f);

    const float* inb = in + (long)n * CI * IHW;

#pragma unroll
    for (int ky = 0; ky < K; ky++) {
        int iys[PXY]; bool ym[PXY];
#pragma unroll
        for (int i = 0; i < PXY; i++) {
            int oy = oy0 + i;
            int iy = oy*S - P + ky;
            ym[i] = (oy < OH) && ((unsigned)iy < (unsigned)IH);
            iys[i] = iy;
        }
#pragma unroll
        for (int kx = 0; kx < K; kx++) {
            int ix = ox*S - P + kx;
            bool xm = (unsigned)ix < (unsigned)IW;
            const float* cp[PXY]; bool m[PXY];
#pragma unroll
            for (int i = 0; i < PXY; i++) {
                m[i] = ym[i] && xm;
                cp[i] = inb + iys[i]*IW + ix;
            }
            const float4* wp4 = (const float4*)(wsm + (ky*K + kx)*CI*16);
#pragma unroll 1
            for (int ci0 = 0; ci0 < CI; ci0 += 4) {
                float v[4][PXY];
#pragma unroll
                for (int u = 0; u < 4; u++)
#pragma unroll
                    for (int i = 0; i < PXY; i++)
                        v[u][i] = m[i] ? __ldg(cp[i] + u*IHW) : 0.f;
                if (PRE) {
#pragma unroll
                    for (int u = 0; u < 4; u++) {
                        float scv = scs[ci0+u], biv = bis[ci0+u];
#pragma unroll
                        for (int i = 0; i < PXY; i++)
                            v[u][i] = m[i] ? fmaxf(fmaf(v[u][i], scv, biv), 0.f) : 0.f;
                    }
                }
#pragma unroll
                for (int u = 0; u < 4; u++) {
                    float4 w0 = wp4[u*4+0], w1 = wp4[u*4+1];
                    float4 w2 = wp4[u*4+2], w3 = wp4[u*4+3];
#pragma unroll
                    for (int i = 0; i < PXY; i++) {
                        fma4(acc[i][0], w0, v[u][i]); fma4(acc[i][1], w1, v[u][i]);
                        fma4(acc[i][2], w2, v[u][i]); fma4(acc[i][3], w3, v[u][i]);
                    }
                }
#pragma unroll
                for (int i = 0; i < PXY; i++) cp[i] += 4*IHW;
                wp4 += 16;
            }
        }
    }

    float bv[16];
#pragma unroll
    for (int j = 0; j < 16; j++) bv[j] = __ldg(cbias + co0 + j);
#pragma unroll
    for (int i = 0; i < PXY; i++) {
        int oy = oy0 + i;
        if (oy >= OH) continue;
        long obase = (((long)n*CO + co0)*OH + oy)*OW + ox;
        float r[16];
        r[0]=acc[i][0].x; r[1]=acc[i][0].y; r[2]=acc[i][0].z; r[3]=acc[i][0].w;
        r[4]=acc[i][1].x; r[5]=acc[i][1].y; r[6]=acc[i][1].z; r[7]=acc[i][1].w;
        r[8]=acc[i][2].x; r[9]=acc[i][2].y; r[10]=acc[i][2].z; r[11]=acc[i][2].w;
        r[12]=acc[i][3].x; r[13]=acc[i][3].y; r[14]=acc[i][3].z; r[15]=acc[i][3].w;
#pragma unroll
        for (int j = 0; j < 16; j++) {
            float vv = r[j] + bv[j];
            if (EPI == 1) vv = 1.f / (1.f + expf(-vv));
            out[obase + (long)j*OHW] = vv;
        }
    }
}

// ==== transposed conv (stride 2, parity classes), shapes compile-time ======
template<int CI, int K, int PXY, int CO, int IH, int IW, int OH, int OW,
         int P, bool PRE, int EPI>
__global__ __launch_bounds__(256, 3) void convt(
    const float* __restrict__ in, const float* __restrict__ wgt,
    const float* __restrict__ cbias,
    const float* __restrict__ sc, const float* __restrict__ bi,
    float* __restrict__ out)
{
    constexpr int IHW = IH * IW;
    constexpr int OHW = OH * OW;

    __shared__ float wsm[K*K*CI*16];
    __shared__ float scs[CI], bis[CI];
    const int tid = threadIdx.x;
    const int co0 = blockIdx.y * 16;

    constexpr int WN = K*K*CI*16;
    for (int idx = tid; idx < WN; idx += 256) {
        int j = idx & 15, r = idx >> 4;
        int ci = r % CI; r /= CI;
        int kx = r % K, ky = r / K;
        wsm[idx] = wgt[((ci*CO + co0 + j)*K + ky)*K + kx];  // (in,out,kh,kw)
    }
    if (PRE) for (int c = tid; c < CI; c += 256) { scs[c] = sc[c]; bis[c] = bi[c]; }
    __syncthreads();

    const int pyc = blockIdx.z >> 1;
    const int pxc = blockIdx.z & 1;
    const int OHc = (OH - pyc + 1) >> 1;
    const int OWc = (OW - pxc + 1) >> 1;
    const int GYc = (OHc + PXY - 1) / PXY;
    const int totalc = BATCH * GYc * OWc;

    int p = blockIdx.x * 256 + tid;
    if (p >= totalc) return;
    const int jx = p % OWc; int t = p / OWc;
    const int gy = t % GYc;
    const int n  = t / GYc;
    const int jy0 = gy * PXY;
    const int ox = pxc + 2*jx;

    float4 acc[PXY][4];
#pragma unroll
    for (int i = 0; i < PXY; i++)
#pragma unroll
        for (int q = 0; q < 4; q++) acc[i][q] = make_float4(0.f,0.f,0.f,0.f);

    const float* inb = in + (long)n * CI * IHW;

#pragma unroll
    for (int ky = 0; ky < K; ky++) {
        int dy = pyc + P - ky;
        if (dy & 1) continue;
        int iy0 = (dy >> 1) + jy0;
        bool ym[PXY]; int iys[PXY];
#pragma unroll
        for (int i = 0; i < PXY; i++) {
            int iy = iy0 + i;
            ym[i] = ((jy0 + i) < OHc) && ((unsigned)iy < (unsigned)IH);
            iys[i] = iy;
        }
#pragma unroll
        for (int kx = 0; kx < K; kx++) {
            int dx = pxc + P - kx;
            if (dx & 1) continue;
            int ix = (dx >> 1) + jx;
            bool xm = (unsigned)ix < (unsigned)IW;
            const float* cp[PXY]; bool m[PXY];
#pragma unroll
            for (int i = 0; i < PXY; i++) {
                m[i] = ym[i] && xm;
                cp[i] = inb + iys[i]*IW + ix;
            }
            const float4* wp4 = (const float4*)(wsm + (ky*K + kx)*CI*16);
#pragma unroll 1
            for (int ci0 = 0; ci0 < CI; ci0 += 4) {
                float v[4][PXY];
#pragma unroll
                for (int u = 0; u < 4; u++)
#pragma unroll
                    for (int i = 0; i < PXY; i++)
                        v[u][i] = m[i] ? __ldg(cp[i] + u*IHW) : 0.f;
                if (PRE) {
#pragma unroll
                    for (int u = 0; u < 4; u++) {
                        float scv = scs[ci0+u], biv = bis[ci0+u];
#pragma unroll
                        for (int i = 0; i < PXY; i++)
                            v[u][i] = m[i] ? fmaxf(fmaf(v[u][i], scv, biv), 0.f) : 0.f;
                    }
                }
#pragma unroll
                for (int u = 0; u < 4; u++) {
                    float4 w0 = wp4[u*4+0], w1 = wp4[u*4+1];
                    float4 w2 = wp4[u*4+2], w3 = wp4[u*4+3];
#pragma unroll
                    for (int i = 0; i < PXY; i++) {
                        fma4(acc[i][0], w0, v[u][i]); fma4(acc[i][1], w1, v[u][i]);
                        fma4(acc[i][2], w2, v[u][i]); fma4(acc[i][3], w3, v[u][i]);
                    }
                }
#pragma unroll
                for (int i = 0; i < PXY; i++) cp[i] += 4*IHW;
                wp4 += 16;
            }
        }
    }

    float bvv[16];
#pragma unroll
    for (int j = 0; j < 16; j++) bvv[j] = __ldg(cbias + co0 + j);
#pragma unroll
    for (int i = 0; i < PXY; i++) {
        if ((jy0 + i) >= OHc) continue;
        int oy = pyc + 2*(jy0 + i);
        long obase = (((long)n*CO + co0)*OH + oy)*OW + ox;
        float r[16];
        r[0]=acc[i][0].x; r[1]=acc[i][0].y; r[2]=acc[i][0].z; r[3]=acc[i][0].w;
        r[4]=acc[i][1].x; r[5]=acc[i][1].y; r[6]=acc[i][1].z; r[7]=acc[i][1].w;
        r[8]=acc[i][2].x; r[9]=acc[i][2].y; r[10]=acc[i][2].z; r[11]=acc[i][2].w;
        r[12]=acc[i][3].x; r[13]=acc[i][3].y; r[14]=acc[i][3].z; r[15]=acc[i][3].w;
#pragma unroll
        for (int j = 0; j < 16; j++) {
            float vv = r[j] + bvv[j];
            if (EPI == 1) vv = 1.f / (1.f + expf(-vv));
            out[obase + (long)j*OHW] = vv;
        }
    }
}

// ================= specialized conv1: 1->16, k1 s2 p1, 96->49 ===============
__global__ __launch_bounds__(256) void conv1_fast(
    const float* __restrict__ x, const float* __restrict__ wgt,
    const float* __restrict__ cbias, float* __restrict__ out)
{
    __shared__ float wv[16], bv[16];
    if (threadIdx.x < 16) { wv[threadIdx.x] = wgt[threadIdx.x]; bv[threadIdx.x] = cbias[threadIdx.x]; }
    __syncthreads();

    int p = blockIdx.x * 256 + threadIdx.x;
    const int total = BATCH*49*49;
    if (p >= total) return;
    const int ox = p % 49; int t = p / 49;
    const int oy = t % 49;
    const int n  = t / 49;
    const int iy = 2*oy - 1, ix = 2*ox - 1;
    float v = (iy >= 0 && ix >= 0) ? __ldg(x + ((long)n*96 + iy)*96 + ix) : 0.f;
    long obase = (((long)n*16)*49 + oy)*49 + ox;
#pragma unroll
    for (int co = 0; co < 16; co++)
        out[obase + (long)co*2401] = fmaf(v, wv[co], bv[co]);
}

// ===== specialized d3: 16->1, k2 s2 p0 transposed (single tap) + sigmoid ====
__global__ __launch_bounds__(256) void d3_fast(
    const float* __restrict__ in, const float* __restrict__ wgt,
    const float* __restrict__ cbias,
    const float* __restrict__ sc, const float* __restrict__ bi,
    float* __restrict__ out)
{
    __shared__ float wsm[64];
    __shared__ float scs[16], bis[16];
    if (threadIdx.x < 64) wsm[threadIdx.x] = wgt[threadIdx.x];
    if (threadIdx.x < 16) { scs[threadIdx.x] = sc[threadIdx.x]; bis[threadIdx.x] = bi[threadIdx.x]; }
    __syncthreads();

    int p = blockIdx.x * 256 + threadIdx.x;
    const int total = BATCH*98*98;
    if (p >= total) return;
    const int ox = p % 98; int t = p / 98;
    const int oy = t % 98;
    const int n  = t / 98;
    const int ky = oy & 1, kx = ox & 1;
    const int iy = oy >> 1, ix = ox >> 1;

    const float* inb = in + ((long)n*16*49 + iy)*49 + ix;
    float v[16];
#pragma unroll
    for (int ci = 0; ci < 16; ci++) v[ci] = __ldg(inb + ci*2401);
    float s = __ldg(cbias);
    const int wo = ky*2 + kx;
#pragma unroll
    for (int ci = 0; ci < 16; ci++) {
        float r = fmaxf(fmaf(v[ci], scs[ci], bis[ci]), 0.f);
        s = fmaf(r, wsm[ci*4 + wo], s);
    }
    out[((long)n*98 + oy)*98 + ox] = 1.f / (1.f + expf(-s));
}

// ---- BN statistics: contiguous row streaming (2-stage, deterministic) -----
template<int C, int HW>
__global__ void bn_partial(const float* __restrict__ in, float* __restrict__ part)
{
    const int c  = blockIdx.x;
    const int sb = blockIdx.y;
    float s = 0.f, q = 0.f;
#pragma unroll 1
    for (int n = sb; n < BATCH; n += NS_RED) {
        const float* row = in + ((long)n*C + c)*HW;
#pragma unroll 4
        for (int i = threadIdx.x; i < HW; i += 256) {
            float v = __ldg(row + i);
            s += v; q += v*v;
        }
    }
    __shared__ float rs[256], rq[256];
    int tid = threadIdx.x;
    rs[tid] = s; rq[tid] = q; __syncthreads();
    for (int o = 128; o > 0; o >>= 1) {
        if (tid < o) { rs[tid] += rs[tid+o]; rq[tid] += rq[tid+o]; }
        __syncthreads();
    }
    if (tid == 0) { part[(c*NS_RED + sb)*2] = rs[0]; part[(c*NS_RED + sb)*2 + 1] = rq[0]; }
}

__global__ void bn_final(const float* __restrict__ part, const float* __restrict__ g,
                         const float* __restrict__ b, float* __restrict__ sc,
                         float* __restrict__ bi, int C, float invN)
{
    int c = blockIdx.x * blockDim.x + threadIdx.x;
    if (c >= C) return;
    float s = 0.f, q = 0.f;
    for (int k = 0; k < NS_RED; k++) { s += part[(c*NS_RED+k)*2]; q += part[(c*NS_RED+k)*2+1]; }
    float m   = s * invN;
    float var = fmaxf(q * invN - m*m, 0.f);
    float scale = g[c] * rsqrtf(var + 1e-5f);
    sc[c] = scale;
    bi[c] = b[c] - m * scale;
}

// ======= fused: z = relu(bn4(t4)) + row L2 norm (one block per row) ========
__global__ void zprep(const float* __restrict__ t4, const float* __restrict__ sc,
                      const float* __restrict__ bi, float* __restrict__ z,
                      float* __restrict__ zn)
{
    const int n = blockIdx.x, tid = threadIdx.x;
    const float* trow = t4 + (long)n * FDIM;
    float* zrow = z + (long)n * FDIM;
    float s = 0.f;
    for (int i = tid; i < FDIM; i += 256) {
        int c = i / 36;
        float v = fmaxf(fmaf(trow[i], sc[c], bi[c]), 0.f);
        zrow[i] = v;
        s += v*v;
    }
    __shared__ float rs[256];
    rs[tid] = s; __syncthreads();
    for (int o = 128; o > 0; o >>= 1) {
        if (tid < o) rs[tid] += rs[tid+o];
        __syncthreads();
    }
    if (tid == 0) zn[n] = sqrtf(rs[0]);
}

// ---------------- row L2 norm (memory) --------------------------------------
__global__ void rownorm(const float* __restrict__ A, float* __restrict__ out, int cols)
{
    const int r = blockIdx.x;
    const float* row = A + (long)r * cols;
    float s = 0.f;
    for (int i = threadIdx.x; i < cols; i += 256) { float v = row[i]; s += v*v; }
    __shared__ float rs[256];
    rs[threadIdx.x] = s; __syncthreads();
    for (int o = 128; o > 0; o >>= 1) {
        if (threadIdx.x < o) rs[threadIdx.x] += rs[threadIdx.x+o];
        __syncthreads();
    }
    if (threadIdx.x == 0) out[r] = sqrtf(rs[0]);
}

// ====== 128x128x8 split-K GEMM (8x8 micro, conflict-free split halves) =====
template<bool BNK, int Mr, int Nr, int Kr>
__global__ __launch_bounds__(256) void gemm128(
    const float* __restrict__ A, const float* __restrict__ Bm,
    float* __restrict__ Cp)
{
    __shared__ float As[8][132];
    __shared__ float Bs[8][132];
    const int tid = threadIdx.x;
    const int row0 = blockIdx.y * 128, col0 = blockIdx.x * 128;
    constexpr int CHUNK = ((Kr/8 + GSPLIT - 1)/GSPLIT)*8;
    const int kb = blockIdx.z * CHUNK;
    const int ke = (Kr < kb + CHUNK) ? Kr : (kb + CHUNK);

    float acc[8][8];
#pragma unroll
    for (int i = 0; i < 8; i++)
#pragma unroll
        for (int j = 0; j < 8; j++) acc[i][j] = 0.f;

    const int ar = tid >> 1, ac = (tid & 1) * 4;
    const int ty = tid >> 4, tx = tid & 15;

    for (int k0 = kb; k0 < ke; k0 += 8) {
        {
            float4 av = *(const float4*)(A + (long)(row0 + ar)*Kr + k0 + ac);
            As[ac+0][ar] = av.x; As[ac+1][ar] = av.y;
            As[ac+2][ar] = av.z; As[ac+3][ar] = av.w;
        }
        if (BNK) {
            int gc = col0 + ar;
            float4 bv = make_float4(0.f,0.f,0.f,0.f);
            if (gc < Nr) bv = *(const float4*)(Bm + (long)gc*Kr + k0 + ac);
            Bs[ac+0][ar] = bv.x; Bs[ac+1][ar] = bv.y;
            Bs[ac+2][ar] = bv.z; Bs[ac+3][ar] = bv.w;
        } else {
            int kk = tid >> 5, j4 = (tid & 31) * 4;
            float4 bv = *(const float4*)(Bm + (long)(k0 + kk)*Nr + col0 + j4);
            *(float4*)&Bs[kk][j4] = bv;
        }
        __syncthreads();
#pragma unroll
        for (int kk = 0; kk < 8; kk++) {
            float4 a0 = *(const float4*)&As[kk][ty*4];
            float4 a1 = *(const float4*)&As[kk][64 + ty*4];
            float4 b0 = *(const float4*)&Bs[kk][tx*4];
            float4 b1 = *(const float4*)&Bs[kk][64 + tx*4];
            float a[8] = {a0.x,a0.y,a0.z,a0.w,a1.x,a1.y,a1.z,a1.w};
            float b[8] = {b0.x,b0.y,b0.z,b0.w,b1.x,b1.y,b1.z,b1.w};
#pragma unroll
            for (int i = 0; i < 8; i++)
#pragma unroll
                for (int j = 0; j < 8; j++) acc[i][j] = fmaf(a[i], b[j], acc[i][j]);
        }
        __syncthreads();
    }

    const long zoff = (long)blockIdx.z * Mr * Nr;
#pragma unroll
    for (int i = 0; i < 8; i++) {
        int gr = row0 + ((i < 4) ? (ty*4 + i) : (64 + ty*4 + i - 4));
        int gc0 = col0 + tx*4;
        int gc1 = col0 + 64 + tx*4;
        float4 s0 = make_float4(acc[i][0], acc[i][1], acc[i][2], acc[i][3]);
        float4 s1 = make_float4(acc[i][4], acc[i][5], acc[i][6], acc[i][7]);
        if (gc0 < Nr) *(float4*)&Cp[zoff + (long)gr*Nr + gc0] = s0;
        if (gc1 < Nr) *(float4*)&Cp[zoff + (long)gr*Nr + gc1] = s1;
    }
}

__global__ void kreduce0(const float* __restrict__ part, float* __restrict__ outp,
                         int Mr, int Nr)
{
    int i = blockIdx.x * blockDim.x + threadIdx.x;
    if (i >= Mr*Nr) return;
    const long stride = (long)Mr * Nr;
    float s = 0.f;
#pragma unroll
    for (int k = 0; k < GSPLIT; k++) s += part[k*stride + i];
    outp[i] = s;
}

// ==== fused: split-K sum + cosine + softmax + hard-shrink + L1 renorm =======
__global__ void addr_fused(const float* __restrict__ gpart, float* __restrict__ w,
                           const float* __restrict__ zn, const float* __restrict__ mn)
{
    __shared__ float srow[MMEM];
    __shared__ float red[256];
    const int n = blockIdx.x, tid = threadIdx.x;
    const long stride = (long)BATCH * MMEM;
    const float zv = zn[n];

    float mx = -1e30f;
    for (int i = tid; i < MMEM; i += 256) {
        long base = (long)n * MMEM + i;
        float s = 0.f;
#pragma unroll
        for (int k = 0; k < GSPLIT; k++) s += gpart[k*stride + base];
        s = s / fmaxf(zv * mn[i], 1e-8f);
        srow[i] = s; mx = fmaxf(mx, s);
    }
    red[tid] = mx; __syncthreads();
    for (int o = 128; o > 0; o >>= 1) { if (tid < o) red[tid] = fmaxf(red[tid], red[tid+o]); __syncthreads(); }
    mx = red[0]; __syncthreads();

    float s = 0.f;
    for (int i = tid; i < MMEM; i += 256) { float e = expf(srow[i] - mx); srow[i] = e; s += e; }
    red[tid] = s; __syncthreads();
    for (int o = 128; o > 0; o >>= 1) { if (tid < o) red[tid] += red[tid+o]; __syncthreads(); }
    float inv = 1.f / red[0]; __syncthreads();

    const float t = 1.f / 2000.f;
    float s2 = 0.f;
    for (int i = tid; i < MMEM; i += 256) {
        float wv = srow[i] * inv;
        float u  = wv - t;
        float sh = (u > 0.f) ? (u * wv / (u + 0.01f)) : 0.f;
        srow[i] = sh; s2 += sh;
    }
    red[tid] = s2; __syncthreads();
    for (int o = 128; o > 0; o >>= 1) { if (tid < o) red[tid] += red[tid+o]; __syncthreads(); }
    float inv2 = 1.f / red[0]; __syncthreads();

    float* row = w + (long)n * MMEM;
    for (int i = tid; i < MMEM; i += 256) row[i] = srow[i] * inv2;
}

// ---------------------------------------------------------------------------
static inline int ceil_div(int a, int b) { return (a + b - 1) / b; }

extern "C" void kernel_launch(void* const* d_in, const int* in_sizes, int n_in,
                              void* d_out, int out_size)
{
    const float* x     = (const float*)d_in[0];
    const float* c1w   = (const float*)d_in[1];  const float* c1b  = (const float*)d_in[2];
    const float* bn1g  = (const float*)d_in[3];  const float* bn1b = (const float*)d_in[4];
    const float* c2w   = (const float*)d_in[5];  const float* c2b  = (const float*)d_in[6];
    const float* bn2g  = (const float*)d_in[7];  const float* bn2b = (const float*)d_in[8];
    const float* c3w   = (const float*)d_in[9];  const float* c3b  = (const float*)d_in[10];
    const float* bn3g  = (const float*)d_in[11]; const float* bn3b = (const float*)d_in[12];
    const float* c4w   = (const float*)d_in[13]; const float* c4b  = (const float*)d_in[14];
    const float* bn4g  = (const float*)d_in[15]; const float* bn4b = (const float*)d_in[16];
    const float* mem   = (const float*)d_in[17];
    const float* d0w   = (const float*)d_in[18]; const float* d0b  = (const float*)d_in[19];
    const float* dbn0g = (const float*)d_in[20]; const float* dbn0b= (const float*)d_in[21];
    const float* d1w   = (const float*)d_in[22]; const float* d1b  = (const float*)d_in[23];
    const float* dbn1g = (const float*)d_in[24]; const float* dbn1b= (const float*)d_in[25];
    const float* d2w   = (const float*)d_in[26]; const float* d2b  = (const float*)d_in[27];
    const float* dbn2g = (const float*)d_in[28]; const float* dbn2b= (const float*)d_in[29];
    const float* d3w   = (const float*)d_in[30]; const float* d3b  = (const float*)d_in[31];
    float* out = (float*)d_out;

    float *bufA, *bufB, *bufC, *t4, *z, *zhat, *w, *zn, *mn, *part, *sc, *bi, *gpart;
    cudaGetSymbolAddress((void**)&bufA, g_bufA);
    cudaGetSymbolAddress((void**)&bufB, g_bufB);
    cudaGetSymbolAddress((void**)&bufC, g_bufC);
    cudaGetSymbolAddress((void**)&t4,   g_t4);
    cudaGetSymbolAddress((void**)&z,    g_z);
    cudaGetSymbolAddress((void**)&zhat, g_zhat);
    cudaGetSymbolAddress((void**)&w,    g_w);
    cudaGetSymbolAddress((void**)&zn,   g_zn);
    cudaGetSymbolAddress((void**)&mn,   g_mn);
    cudaGetSymbolAddress((void**)&part, g_part);
    cudaGetSymbolAddress((void**)&sc,   g_sc);
    cudaGetSymbolAddress((void**)&bi,   g_bi);
    cudaGetSymbolAddress((void**)&gpart, g_gpart);

    const int TB = 256;

    // ---- encoder ----
    // conv1: 1->16, k1 s2 p1, 96 -> 49 (specialized)
    {
        int total = BATCH*49*49;
        conv1_fast<<<ceil_div(total,TB), TB>>>(x, c1w, c1b, bufA);
        bn_partial<16,2401><<<dim3(16,NS_RED), TB>>>(bufA, part);
        bn_final<<<1, 64>>>(part, bn1g, bn1b, sc, bi, 16, 1.f/((float)BATCH*2401));
    }
    // conv2: 16->32, k3 s2 p1, 49 -> 25
    {
        int total = BATCH*13*25;
        convd<16,3,2,2, 32,49,49,25,25,1, true,0><<<dim3(ceil_div(total,TB),2), TB>>>(
            bufA, c2w, c2b, sc, bi, bufB);
        bn_partial<32,625><<<dim3(32,NS_RED), TB>>>(bufB, part);
        bn_final<<<1, 64>>>(part, bn2g, bn2b, sc, bi, 32, 1.f/((float)BATCH*625));
    }
    // conv3: 32->64, k3 s2 p1, 25 -> 13
    {
        int total = BATCH*7*13;
        convd<32,3,2,2, 64,25,25,13,13,1, true,0><<<dim3(ceil_div(total,TB),4), TB>>>(
            bufB, c3w, c3b, sc, bi, bufC);
        bn_partial<64,169><<<dim3(64,NS_RED), TB>>>(bufC, part);
        bn_final<<<1, 64>>>(part, bn3g, bn3b, sc, bi, 64, 1.f/((float)BATCH*169));
    }
    // conv4: 64->64, k3 s2 p0, 13 -> 6
    {
        int total = BATCH*3*6;
        convd<64,3,2,2, 64,13,13,6,6,0, true,0><<<dim3(ceil_div(total,TB),4), TB>>>(
            bufC, c4w, c4b, sc, bi, t4);
        bn_partial<64,36><<<dim3(64,NS_RED), TB>>>(t4, part);
        bn_final<<<1, 64>>>(part, bn4g, bn4b, sc, bi, 64, 1.f/((float)BATCH*36));
    }

    // ---- memory addressing ----
    {
        zprep<<<BATCH, 256>>>(t4, sc, bi, z, zn);
        rownorm<<<MMEM, 256>>>(mem, mn, FDIM);
        gemm128<true, BATCH, MMEM, FDIM><<<dim3(ceil_div(MMEM,128), BATCH/128, GSPLIT), 256>>>(
            z, mem, gpart);
        addr_fused<<<BATCH, 256>>>(gpart, w, zn, mn);
        gemm128<false, BATCH, FDIM, MMEM><<<dim3(FDIM/128, BATCH/128, GSPLIT), 256>>>(
            w, mem, gpart);
        kreduce0<<<ceil_div(BATCH*FDIM,TB), TB>>>(gpart, zhat, BATCH, FDIM);
    }

    // ---- decoder ----
    // d0: 64->64, k3 s2 p0, 6 -> 13
    {
        int maxtot = BATCH * 4 * 7;
        convt<64,3,2, 64,6,6,13,13,0, false,0><<<dim3(ceil_div(maxtot,TB),4,4), TB>>>(
            zhat, d0w, d0b, nullptr, nullptr, bufC);
        bn_partial<64,169><<<dim3(64,NS_RED), TB>>>(bufC, part);
        bn_final<<<1, 64>>>(part, dbn0g, dbn0b, sc, bi, 64, 1.f/((float)BATCH*169));
    }
    // d1: 64->32, k3 s2 p1, 13 -> 25
    {
        int maxtot = BATCH * 7 * 13;
        convt<64,3,2, 32,13,13,25,25,1, true,0><<<dim3(ceil_div(maxtot,TB),2,4), TB>>>(
            bufC, d1w, d1b, sc, bi, bufB);
        bn_partial<32,625><<<dim3(32,NS_RED), TB>>>(bufB, part);
        bn_final<<<1, 64>>>(part, dbn1g, dbn1b, sc, bi, 32, 1.f/((float)BATCH*625));
    }
    // d2: 32->16, k2 s2 p1 op1, 25 -> 49
    {
        int maxtot = BATCH * 13 * 25;
        convt<32,2,2, 16,25,25,49,49,1, true,0><<<dim3(ceil_div(maxtot,TB),1,4), TB>>>(
            bufB, d2w, d2b, sc, bi, bufA);
        bn_partial<16,2401><<<dim3(16,NS_RED), TB>>>(bufA, part);
        bn_final<<<1, 64>>>(part, dbn2g, dbn2b, sc, bi, 16, 1.f/((float)BATCH*2401));
    }
    // d3: 16->1, k2 s2 p0, 49 -> 98, sigmoid -> out (specialized single-tap)
    {
        int total = BATCH*98*98;
        d3_fast<<<ceil_div(total,TB), TB>>>(bufA, d3w, d3b, sc, bi, out);
    }
}

// round 15
// speedup vs baseline: 1.0233x; 1.0233x over previous
#include <cuda_runtime.h>
#include <math.h>

#define BATCH 512
#define MMEM  2000
#define FDIM  2304
#define NS_RED 64
#define GSPLIT 8

// ---------------- scratch (device globals: allocation-free) ----------------
__device__ float g_bufA[512*16*49*49];
__device__ float g_bufB[512*32*25*25];
__device__ float g_bufC[512*64*13*13];
__device__ float g_t4  [512*2304];
__device__ float g_z   [512*2304];
__device__ float g_zhat[512*2304];
__device__ float g_w   [512*2000];
__device__ float g_zn  [512];
__device__ float g_mn  [2000];
__device__ float g_part[64*NS_RED*2];
__device__ float g_sc  [64];
__device__ float g_bi  [64];
__device__ float g_gpart[GSPLIT*512*2304];

__device__ __forceinline__ void fma4(float4& a, float4 w, float v) {
    a.x = fmaf(v, w.x, a.x); a.y = fmaf(v, w.y, a.y);
    a.z = fmaf(v, w.z, a.z); a.w = fmaf(v, w.w, a.w);
}

// ======= direct conv, ALL shapes compile-time, incremented pointers ========
template<int CI, int K, int S, int PXY, int CO, int IH, int IW, int OH, int OW,
         int P, bool PRE, int EPI>
__global__ __launch_bounds__(256, 3) void convd(
    const float* __restrict__ in, const float* __restrict__ wgt,
    const float* __restrict__ cbias,
    const float* __restrict__ sc, const float* __restrict__ bi,
    float* __restrict__ out)
{
    constexpr int GY = (OH + PXY - 1) / PXY;
    constexpr int TOTAL = BATCH * GY * OW;
    constexpr int IHW = IH * IW;
    constexpr int OHW = OH * OW;

    __shared__ float wsm[K*K*CI*16];
    __shared__ float scs[CI], bis[CI];
    const int tid = threadIdx.x;
    const int co0 = blockIdx.y * 16;

    constexpr int WN = K*K*CI*16;
    for (int idx = tid; idx < WN; idx += 256) {
        int j = idx & 15, r = idx >> 4;
        int ci = r % CI; r /= CI;
        int kx = r % K, ky = r / K;
        wsm[idx] = wgt[(((co0 + j)*CI + ci)*K + ky)*K + kx];
    }
    if (PRE) for (int c = tid; c < CI; c += 256) { scs[c] = sc[c]; bis[c] = bi[c]; }
    __syncthreads();

    int p = blockIdx.x * 256 + tid;
    if (p >= TOTAL) return;
    const int ox = p % OW; int t = p / OW;
    const int gy = t % GY;
    const int n  = t / GY;
    const int oy0 = gy * PXY;

    float4 acc[PXY][4];
#pragma unroll
    for (int i = 0; i < PXY; i++)
#pragma unroll
        for (int q = 0; q < 4; q++) acc[i][q] = make_float4(0.f,0.f,0.f,0.f);

    const float* inb = in + (long)n * CI * IHW;

#pragma unroll
    for (int ky = 0; ky < K; ky++) {
        int iys[PXY]; bool ym[PXY];
#pragma unroll
        for (int i = 0; i < PXY; i++) {
            int oy = oy0 + i;
            int iy = oy*S - P + ky;
            ym[i] = (oy < OH) && ((unsigned)iy < (unsigned)IH);
            iys[i] = iy;
        }
#pragma unroll
        for (int kx = 0; kx < K; kx++) {
            int ix = ox*S - P + kx;
            bool xm = (unsigned)ix < (unsigned)IW;
            const float* cp[PXY]; bool m[PXY];
#pragma unroll
            for (int i = 0; i < PXY; i++) {
                m[i] = ym[i] && xm;
                cp[i] = inb + iys[i]*IW + ix;
            }
            const float4* wp4 = (const float4*)(wsm + (ky*K + kx)*CI*16);
#pragma unroll 1
            for (int ci0 = 0; ci0 < CI; ci0 += 4) {
                float v[4][PXY];
#pragma unroll
                for (int u = 0; u < 4; u++)
#pragma unroll
                    for (int i = 0; i < PXY; i++)
                        v[u][i] = m[i] ? __ldg(cp[i] + u*IHW) : 0.f;
                if (PRE) {
#pragma unroll
                    for (int u = 0; u < 4; u++) {
                        float scv = scs[ci0+u], biv = bis[ci0+u];
#pragma unroll
                        for (int i = 0; i < PXY; i++)
                            v[u][i] = m[i] ? fmaxf(fmaf(v[u][i], scv, biv), 0.f) : 0.f;
                    }
                }
#pragma unroll
                for (int u = 0; u < 4; u++) {
                    float4 w0 = wp4[u*4+0], w1 = wp4[u*4+1];
                    float4 w2 = wp4[u*4+2], w3 = wp4[u*4+3];
#pragma unroll
                    for (int i = 0; i < PXY; i++) {
                        fma4(acc[i][0], w0, v[u][i]); fma4(acc[i][1], w1, v[u][i]);
                        fma4(acc[i][2], w2, v[u][i]); fma4(acc[i][3], w3, v[u][i]);
                    }
                }
#pragma unroll
                for (int i = 0; i < PXY; i++) cp[i] += 4*IHW;
                wp4 += 16;
            }
        }
    }

    float bv[16];
#pragma unroll
    for (int j = 0; j < 16; j++) bv[j] = __ldg(cbias + co0 + j);
#pragma unroll
    for (int i = 0; i < PXY; i++) {
        int oy = oy0 + i;
        if (oy >= OH) continue;
        long obase = (((long)n*CO + co0)*OH + oy)*OW + ox;
        float r[16];
        r[0]=acc[i][0].x; r[1]=acc[i][0].y; r[2]=acc[i][0].z; r[3]=acc[i][0].w;
        r[4]=acc[i][1].x; r[5]=acc[i][1].y; r[6]=acc[i][1].z; r[7]=acc[i][1].w;
        r[8]=acc[i][2].x; r[9]=acc[i][2].y; r[10]=acc[i][2].z; r[11]=acc[i][2].w;
        r[12]=acc[i][3].x; r[13]=acc[i][3].y; r[14]=acc[i][3].z; r[15]=acc[i][3].w;
#pragma unroll
        for (int j = 0; j < 16; j++) {
            float vv = r[j] + bv[j];
            if (EPI == 1) vv = 1.f / (1.f + expf(-vv));
            out[obase + (long)j*OHW] = vv;
        }
    }
}

// ==== transposed conv (stride 2, parity classes), shapes compile-time ======
template<int CI, int K, int PXY, int CO, int IH, int IW, int OH, int OW,
         int P, bool PRE, int EPI>
__global__ __launch_bounds__(256, 3) void convt(
    const float* __restrict__ in, const float* __restrict__ wgt,
    const float* __restrict__ cbias,
    const float* __restrict__ sc, const float* __restrict__ bi,
    float* __restrict__ out)
{
    constexpr int IHW = IH * IW;
    constexpr int OHW = OH * OW;

    __shared__ float wsm[K*K*CI*16];
    __shared__ float scs[CI], bis[CI];
    const int tid = threadIdx.x;
    const int co0 = blockIdx.y * 16;

    constexpr int WN = K*K*CI*16;
    for (int idx = tid; idx < WN; idx += 256) {
        int j = idx & 15, r = idx >> 4;
        int ci = r % CI; r /= CI;
        int kx = r % K, ky = r / K;
        wsm[idx] = wgt[((ci*CO + co0 + j)*K + ky)*K + kx];  // (in,out,kh,kw)
    }
    if (PRE) for (int c = tid; c < CI; c += 256) { scs[c] = sc[c]; bis[c] = bi[c]; }
    __syncthreads();

    const int pyc = blockIdx.z >> 1;
    const int pxc = blockIdx.z & 1;
    const int OHc = (OH - pyc + 1) >> 1;
    const int OWc = (OW - pxc + 1) >> 1;
    const int GYc = (OHc + PXY - 1) / PXY;
    const int totalc = BATCH * GYc * OWc;

    int p = blockIdx.x * 256 + tid;
    if (p >= totalc) return;
    const int jx = p % OWc; int t = p / OWc;
    const int gy = t % GYc;
    const int n  = t / GYc;
    const int jy0 = gy * PXY;
    const int ox = pxc + 2*jx;

    float4 acc[PXY][4];
#pragma unroll
    for (int i = 0; i < PXY; i++)
#pragma unroll
        for (int q = 0; q < 4; q++) acc[i][q] = make_float4(0.f,0.f,0.f,0.f);

    const float* inb = in + (long)n * CI * IHW;

#pragma unroll
    for (int ky = 0; ky < K; ky++) {
        int dy = pyc + P - ky;
        if (dy & 1) continue;
        int iy0 = (dy >> 1) + jy0;
        bool ym[PXY]; int iys[PXY];
#pragma unroll
        for (int i = 0; i < PXY; i++) {
            int iy = iy0 + i;
            ym[i] = ((jy0 + i) < OHc) && ((unsigned)iy < (unsigned)IH);
            iys[i] = iy;
        }
#pragma unroll
        for (int kx = 0; kx < K; kx++) {
            int dx = pxc + P - kx;
            if (dx & 1) continue;
            int ix = (dx >> 1) + jx;
            bool xm = (unsigned)ix < (unsigned)IW;
            const float* cp[PXY]; bool m[PXY];
#pragma unroll
            for (int i = 0; i < PXY; i++) {
                m[i] = ym[i] && xm;
                cp[i] = inb + iys[i]*IW + ix;
            }
            const float4* wp4 = (const float4*)(wsm + (ky*K + kx)*CI*16);
#pragma unroll 1
            for (int ci0 = 0; ci0 < CI; ci0 += 4) {
                float v[4][PXY];
#pragma unroll
                for (int u = 0; u < 4; u++)
#pragma unroll
                    for (int i = 0; i < PXY; i++)
                        v[u][i] = m[i] ? __ldg(cp[i] + u*IHW) : 0.f;
                if (PRE) {
#pragma unroll
                    for (int u = 0; u < 4; u++) {
                        float scv = scs[ci0+u], biv = bis[ci0+u];
#pragma unroll
                        for (int i = 0; i < PXY; i++)
                            v[u][i] = m[i] ? fmaxf(fmaf(v[u][i], scv, biv), 0.f) : 0.f;
                    }
                }
#pragma unroll
                for (int u = 0; u < 4; u++) {
                    float4 w0 = wp4[u*4+0], w1 = wp4[u*4+1];
                    float4 w2 = wp4[u*4+2], w3 = wp4[u*4+3];
#pragma unroll
                    for (int i = 0; i < PXY; i++) {
                        fma4(acc[i][0], w0, v[u][i]); fma4(acc[i][1], w1, v[u][i]);
                        fma4(acc[i][2], w2, v[u][i]); fma4(acc[i][3], w3, v[u][i]);
                    }
                }
#pragma unroll
                for (int i = 0; i < PXY; i++) cp[i] += 4*IHW;
                wp4 += 16;
            }
        }
    }

    float bvv[16];
#pragma unroll
    for (int j = 0; j < 16; j++) bvv[j] = __ldg(cbias + co0 + j);
#pragma unroll
    for (int i = 0; i < PXY; i++) {
        if ((jy0 + i) >= OHc) continue;
        int oy = pyc + 2*(jy0 + i);
        long obase = (((long)n*CO + co0)*OH + oy)*OW + ox;
        float r[16];
        r[0]=acc[i][0].x; r[1]=acc[i][0].y; r[2]=acc[i][0].z; r[3]=acc[i][0].w;
        r[4]=acc[i][1].x; r[5]=acc[i][1].y; r[6]=acc[i][1].z; r[7]=acc[i][1].w;
        r[8]=acc[i][2].x; r[9]=acc[i][2].y; r[10]=acc[i][2].z; r[11]=acc[i][2].w;
        r[12]=acc[i][3].x; r[13]=acc[i][3].y; r[14]=acc[i][3].z; r[15]=acc[i][3].w;
#pragma unroll
        for (int j = 0; j < 16; j++) {
            float vv = r[j] + bvv[j];
            if (EPI == 1) vv = 1.f / (1.f + expf(-vv));
            out[obase + (long)j*OHW] = vv;
        }
    }
}

// ================= specialized conv1: 1->16, k1 s2 p1, 96->49 ===============
__global__ __launch_bounds__(256) void conv1_fast(
    const float* __restrict__ x, const float* __restrict__ wgt,
    const float* __restrict__ cbias, float* __restrict__ out)
{
    __shared__ float wv[16], bv[16];
    if (threadIdx.x < 16) { wv[threadIdx.x] = wgt[threadIdx.x]; bv[threadIdx.x] = cbias[threadIdx.x]; }
    __syncthreads();

    int p = blockIdx.x * 256 + threadIdx.x;
    const int total = BATCH*49*49;
    if (p >= total) return;
    const int ox = p % 49; int t = p / 49;
    const int oy = t % 49;
    const int n  = t / 49;
    const int iy = 2*oy - 1, ix = 2*ox - 1;
    float v = (iy >= 0 && ix >= 0) ? __ldg(x + ((long)n*96 + iy)*96 + ix) : 0.f;
    long obase = (((long)n*16)*49 + oy)*49 + ox;
#pragma unroll
    for (int co = 0; co < 16; co++)
        out[obase + (long)co*2401] = fmaf(v, wv[co], bv[co]);
}

// ===== specialized d3: 16->1, k2 s2 p0 transposed (single tap) + sigmoid ====
__global__ __launch_bounds__(256) void d3_fast(
    const float* __restrict__ in, const float* __restrict__ wgt,
    const float* __restrict__ cbias,
    const float* __restrict__ sc, const float* __restrict__ bi,
    float* __restrict__ out)
{
    __shared__ float wsm[64];
    __shared__ float scs[16], bis[16];
    if (threadIdx.x < 64) wsm[threadIdx.x] = wgt[threadIdx.x];
    if (threadIdx.x < 16) { scs[threadIdx.x] = sc[threadIdx.x]; bis[threadIdx.x] = bi[threadIdx.x]; }
    __syncthreads();

    int p = blockIdx.x * 256 + threadIdx.x;
    const int total = BATCH*98*98;
    if (p >= total) return;
    const int ox = p % 98; int t = p / 98;
    const int oy = t % 98;
    const int n  = t / 98;
    const int ky = oy & 1, kx = ox & 1;
    const int iy = oy >> 1, ix = ox >> 1;

    const float* inb = in + ((long)n*16*49 + iy)*49 + ix;
    float v[16];
#pragma unroll
    for (int ci = 0; ci < 16; ci++) v[ci] = __ldg(inb + ci*2401);
    float s = __ldg(cbias);
    const int wo = ky*2 + kx;
#pragma unroll
    for (int ci = 0; ci < 16; ci++) {
        float r = fmaxf(fmaf(v[ci], scs[ci], bis[ci]), 0.f);
        s = fmaf(r, wsm[ci*4 + wo], s);
    }
    out[((long)n*98 + oy)*98 + ox] = 1.f / (1.f + expf(-s));
}

// ---- BN statistics (flat index, MLP-4 unrolled, deterministic) ------------
template<int C, int HW>
__global__ void bn_partial(const float* __restrict__ in, float* __restrict__ part)
{
    const int c  = blockIdx.x;
    const int sb = blockIdx.y;
    constexpr long TOT = (long)BATCH * HW;
    const long stride = 256L * NS_RED;
    float s = 0.f, q = 0.f;
#pragma unroll 4
    for (long e = (long)sb*256 + threadIdx.x; e < TOT; e += stride) {
        int n = (int)(e / HW), i = (int)(e % HW);
        float v = __ldg(in + ((long)n*C + c)*HW + i);
        s += v; q += v*v;
    }
    __shared__ float rs[256], rq[256];
    int tid = threadIdx.x;
    rs[tid] = s; rq[tid] = q; __syncthreads();
    for (int o = 128; o > 0; o >>= 1) {
        if (tid < o) { rs[tid] += rs[tid+o]; rq[tid] += rq[tid+o]; }
        __syncthreads();
    }
    if (tid == 0) { part[(c*NS_RED + sb)*2] = rs[0]; part[(c*NS_RED + sb)*2 + 1] = rq[0]; }
}

__global__ void bn_final(const float* __restrict__ part, const float* __restrict__ g,
                         const float* __restrict__ b, float* __restrict__ sc,
                         float* __restrict__ bi, int C, float invN)
{
    int c = blockIdx.x * blockDim.x + threadIdx.x;
    if (c >= C) return;
    float s = 0.f, q = 0.f;
    for (int k = 0; k < NS_RED; k++) { s += part[(c*NS_RED+k)*2]; q += part[(c*NS_RED+k)*2+1]; }
    float m   = s * invN;
    float var = fmaxf(q * invN - m*m, 0.f);
    float scale = g[c] * rsqrtf(var + 1e-5f);
    sc[c] = scale;
    bi[c] = b[c] - m * scale;
}

// ======= fused: z = relu(bn4(t4)) + row L2 norm (one block per row) ========
__global__ void zprep(const float* __restrict__ t4, const float* __restrict__ sc,
                      const float* __restrict__ bi, float* __restrict__ z,
                      float* __restrict__ zn)
{
    const int n = blockIdx.x, tid = threadIdx.x;
    const float* trow = t4 + (long)n * FDIM;
    float* zrow = z + (long)n * FDIM;
    float s = 0.f;
    for (int i = tid; i < FDIM; i += 256) {
        int c = i / 36;
        float v = fmaxf(fmaf(trow[i], sc[c], bi[c]), 0.f);
        zrow[i] = v;
        s += v*v;
    }
    __shared__ float rs[256];
    rs[tid] = s; __syncthreads();
    for (int o = 128; o > 0; o >>= 1) {
        if (tid < o) rs[tid] += rs[tid+o];
        __syncthreads();
    }
    if (tid == 0) zn[n] = sqrtf(rs[0]);
}

// ---------------- row L2 norm (memory) --------------------------------------
__global__ void rownorm(const float* __restrict__ A, float* __restrict__ out, int cols)
{
    const int r = blockIdx.x;
    const float* row = A + (long)r * cols;
    float s = 0.f;
    for (int i = threadIdx.x; i < cols; i += 256) { float v = row[i]; s += v*v; }
    __shared__ float rs[256];
    rs[threadIdx.x] = s; __syncthreads();
    for (int o = 128; o > 0; o >>= 1) {
        if (threadIdx.x < o) rs[threadIdx.x] += rs[threadIdx.x+o];
        __syncthreads();
    }
    if (threadIdx.x == 0) out[r] = sqrtf(rs[0]);
}

// ====== 128x128x8 split-K GEMM (8x8 micro, conflict-free split halves) =====
template<bool BNK, int Mr, int Nr, int Kr>
__global__ __launch_bounds__(256) void gemm128(
    const float* __restrict__ A, const float* __restrict__ Bm,
    float* __restrict__ Cp)
{
    __shared__ float As[8][132];
    __shared__ float Bs[8][132];
    const int tid = threadIdx.x;
    const int row0 = blockIdx.y * 128, col0 = blockIdx.x * 128;
    constexpr int CHUNK = ((Kr/8 + GSPLIT - 1)/GSPLIT)*8;
    const int kb = blockIdx.z * CHUNK;
    const int ke = (Kr < kb + CHUNK) ? Kr : (kb + CHUNK);

    float acc[8][8];
#pragma unroll
    for (int i = 0; i < 8; i++)
#pragma unroll
        for (int j = 0; j < 8; j++) acc[i][j] = 0.f;

    const int ar = tid >> 1, ac = (tid & 1) * 4;
    const int ty = tid >> 4, tx = tid & 15;

    for (int k0 = kb; k0 < ke; k0 += 8) {
        {
            float4 av = *(const float4*)(A + (long)(row0 + ar)*Kr + k0 + ac);
            As[ac+0][ar] = av.x; As[ac+1][ar] = av.y;
            As[ac+2][ar] = av.z; As[ac+3][ar] = av.w;
        }
        if (BNK) {
            int gc = col0 + ar;
            float4 bv = make_float4(0.f,0.f,0.f,0.f);
            if (gc < Nr) bv = *(const float4*)(Bm + (long)gc*Kr + k0 + ac);
            Bs[ac+0][ar] = bv.x; Bs[ac+1][ar] = bv.y;
            Bs[ac+2][ar] = bv.z; Bs[ac+3][ar] = bv.w;
        } else {
            int kk = tid >> 5, j4 = (tid & 31) * 4;
            float4 bv = *(const float4*)(Bm + (long)(k0 + kk)*Nr + col0 + j4);
            *(float4*)&Bs[kk][j4] = bv;
        }
        __syncthreads();
#pragma unroll
        for (int kk = 0; kk < 8; kk++) {
            float4 a0 = *(const float4*)&As[kk][ty*4];
            float4 a1 = *(const float4*)&As[kk][64 + ty*4];
            float4 b0 = *(const float4*)&Bs[kk][tx*4];
            float4 b1 = *(const float4*)&Bs[kk][64 + tx*4];
            float a[8] = {a0.x,a0.y,a0.z,a0.w,a1.x,a1.y,a1.z,a1.w};
            float b[8] = {b0.x,b0.y,b0.z,b0.w,b1.x,b1.y,b1.z,b1.w};
#pragma unroll
            for (int i = 0; i < 8; i++)
#pragma unroll
                for (int j = 0; j < 8; j++) acc[i][j] = fmaf(a[i], b[j], acc[i][j]);
        }
        __syncthreads();
    }

    const long zoff = (long)blockIdx.z * Mr * Nr;
#pragma unroll
    for (int i = 0; i < 8; i++) {
        int gr = row0 + ((i < 4) ? (ty*4 + i) : (64 + ty*4 + i - 4));
        int gc0 = col0 + tx*4;
        int gc1 = col0 + 64 + tx*4;
        float4 s0 = make_float4(acc[i][0], acc[i][1], acc[i][2], acc[i][3]);
        float4 s1 = make_float4(acc[i][4], acc[i][5], acc[i][6], acc[i][7]);
        if (gc0 < Nr) *(float4*)&Cp[zoff + (long)gr*Nr + gc0] = s0;
        if (gc1 < Nr) *(float4*)&Cp[zoff + (long)gr*Nr + gc1] = s1;
    }
}

__global__ void kreduce0(const float* __restrict__ part, float* __restrict__ outp,
                         int Mr, int Nr)
{
    int i = blockIdx.x * blockDim.x + threadIdx.x;
    if (i >= Mr*Nr) return;
    const long stride = (long)Mr * Nr;
    float s = 0.f;
#pragma unroll
    for (int k = 0; k < GSPLIT; k++) s += part[k*stride + i];
    outp[i] = s;
}

// ==== fused: split-K sum + cosine + softmax + hard-shrink + L1 renorm =======
__global__ void addr_fused(const float* __restrict__ gpart, float* __restrict__ w,
                           const float* __restrict__ zn, const float* __restrict__ mn)
{
    __shared__ float srow[MMEM];
    __shared__ float red[256];
    const int n = blockIdx.x, tid = threadIdx.x;
    const long stride = (long)BATCH * MMEM;
    const float zv = zn[n];

    float mx = -1e30f;
    for (int i = tid; i < MMEM; i += 256) {
        long base = (long)n * MMEM + i;
        float s = 0.f;
#pragma unroll
        for (int k = 0; k < GSPLIT; k++) s += gpart[k*stride + base];
        s = s / fmaxf(zv * mn[i], 1e-8f);
        srow[i] = s; mx = fmaxf(mx, s);
    }
    red[tid] = mx; __syncthreads();
    for (int o = 128; o > 0; o >>= 1) { if (tid < o) red[tid] = fmaxf(red[tid], red[tid+o]); __syncthreads(); }
    mx = red[0]; __syncthreads();

    float s = 0.f;
    for (int i = tid; i < MMEM; i += 256) { float e = expf(srow[i] - mx); srow[i] = e; s += e; }
    red[tid] = s; __syncthreads();
    for (int o = 128; o > 0; o >>= 1) { if (tid < o) red[tid] += red[tid+o]; __syncthreads(); }
    float inv = 1.f / red[0]; __syncthreads();

    const float t = 1.f / 2000.f;
    float s2 = 0.f;
    for (int i = tid; i < MMEM; i += 256) {
        float wv = srow[i] * inv;
        float u  = wv - t;
        float sh = (u > 0.f) ? (u * wv / (u + 0.01f)) : 0.f;
        srow[i] = sh; s2 += sh;
    }
    red[tid] = s2; __syncthreads();
    for (int o = 128; o > 0; o >>= 1) { if (tid < o) red[tid] += red[tid+o]; __syncthreads(); }
    float inv2 = 1.f / red[0]; __syncthreads();

    float* row = w + (long)n * MMEM;
    for (int i = tid; i < MMEM; i += 256) row[i] = srow[i] * inv2;
}

// ---------------------------------------------------------------------------
static inline int ceil_div(int a, int b) { return (a + b - 1) / b; }

extern "C" void kernel_launch(void* const* d_in, const int* in_sizes, int n_in,
                              void* d_out, int out_size)
{
    const float* x     = (const float*)d_in[0];
    const float* c1w   = (const float*)d_in[1];  const float* c1b  = (const float*)d_in[2];
    const float* bn1g  = (const float*)d_in[3];  const float* bn1b = (const float*)d_in[4];
    const float* c2w   = (const float*)d_in[5];  const float* c2b  = (const float*)d_in[6];
    const float* bn2g  = (const float*)d_in[7];  const float* bn2b = (const float*)d_in[8];
    const float* c3w   = (const float*)d_in[9];  const float* c3b  = (const float*)d_in[10];
    const float* bn3g  = (const float*)d_in[11]; const float* bn3b = (const float*)d_in[12];
    const float* c4w   = (const float*)d_in[13]; const float* c4b  = (const float*)d_in[14];
    const float* bn4g  = (const float*)d_in[15]; const float* bn4b = (const float*)d_in[16];
    const float* mem   = (const float*)d_in[17];
    const float* d0w   = (const float*)d_in[18]; const float* d0b  = (const float*)d_in[19];
    const float* dbn0g = (const float*)d_in[20]; const float* dbn0b= (const float*)d_in[21];
    const float* d1w   = (const float*)d_in[22]; const float* d1b  = (const float*)d_in[23];
    const float* dbn1g = (const float*)d_in[24]; const float* dbn1b= (const float*)d_in[25];
    const float* d2w   = (const float*)d_in[26]; const float* d2b  = (const float*)d_in[27];
    const float* dbn2g = (const float*)d_in[28]; const float* dbn2b= (const float*)d_in[29];
    const float* d3w   = (const float*)d_in[30]; const float* d3b  = (const float*)d_in[31];
    float* out = (float*)d_out;

    float *bufA, *bufB, *bufC, *t4, *z, *zhat, *w, *zn, *mn, *part, *sc, *bi, *gpart;
    cudaGetSymbolAddress((void**)&bufA, g_bufA);
    cudaGetSymbolAddress((void**)&bufB, g_bufB);
    cudaGetSymbolAddress((void**)&bufC, g_bufC);
    cudaGetSymbolAddress((void**)&t4,   g_t4);
    cudaGetSymbolAddress((void**)&z,    g_z);
    cudaGetSymbolAddress((void**)&zhat, g_zhat);
    cudaGetSymbolAddress((void**)&w,    g_w);
    cudaGetSymbolAddress((void**)&zn,   g_zn);
    cudaGetSymbolAddress((void**)&mn,   g_mn);
    cudaGetSymbolAddress((void**)&part, g_part);
    cudaGetSymbolAddress((void**)&sc,   g_sc);
    cudaGetSymbolAddress((void**)&bi,   g_bi);
    cudaGetSymbolAddress((void**)&gpart, g_gpart);

    const int TB = 256;

    // ---- encoder ----
    // conv1: 1->16, k1 s2 p1, 96 -> 49 (specialized)
    {
        int total = BATCH*49*49;
        conv1_fast<<<ceil_div(total,TB), TB>>>(x, c1w, c1b, bufA);
        bn_partial<16,2401><<<dim3(16,NS_RED), TB>>>(bufA, part);
        bn_final<<<1, 64>>>(part, bn1g, bn1b, sc, bi, 16, 1.f/((float)BATCH*2401));
    }
    // conv2: 16->32, k3 s2 p1, 49 -> 25
    {
        int total = BATCH*13*25;
        convd<16,3,2,2, 32,49,49,25,25,1, true,0><<<dim3(ceil_div(total,TB),2), TB>>>(
            bufA, c2w, c2b, sc, bi, bufB);
        bn_partial<32,625><<<dim3(32,NS_RED), TB>>>(bufB, part);
        bn_final<<<1, 64>>>(part, bn2g, bn2b, sc, bi, 32, 1.f/((float)BATCH*625));
    }
    // conv3: 32->64, k3 s2 p1, 25 -> 13
    {
        int total = BATCH*7*13;
        convd<32,3,2,2, 64,25,25,13,13,1, true,0><<<dim3(ceil_div(total,TB),4), TB>>>(
            bufB, c3w, c3b, sc, bi, bufC);
        bn_partial<64,169><<<dim3(64,NS_RED), TB>>>(bufC, part);
        bn_final<<<1, 64>>>(part, bn3g, bn3b, sc, bi, 64, 1.f/((float)BATCH*169));
    }
    // conv4: 64->64, k3 s2 p0, 13 -> 6
    {
        int total = BATCH*3*6;
        convd<64,3,2,2, 64,13,13,6,6,0, true,0><<<dim3(ceil_div(total,TB),4), TB>>>(
            bufC, c4w, c4b, sc, bi, t4);
        bn_partial<64,36><<<dim3(64,NS_RED), TB>>>(t4, part);
        bn_final<<<1, 64>>>(part, bn4g, bn4b, sc, bi, 64, 1.f/((float)BATCH*36));
    }

    // ---- memory addressing ----
    {
        zprep<<<BATCH, 256>>>(t4, sc, bi, z, zn);
        rownorm<<<MMEM, 256>>>(mem, mn, FDIM);
        gemm128<true, BATCH, MMEM, FDIM><<<dim3(ceil_div(MMEM,128), BATCH/128, GSPLIT), 256>>>(
            z, mem, gpart);
        addr_fused<<<BATCH, 256>>>(gpart, w, zn, mn);
        gemm128<false, BATCH, FDIM, MMEM><<<dim3(FDIM/128, BATCH/128, GSPLIT), 256>>>(
            w, mem, gpart);
        kreduce0<<<ceil_div(BATCH*FDIM,TB), TB>>>(gpart, zhat, BATCH, FDIM);
    }

    // ---- decoder ----
    // d0: 64->64, k3 s2 p0, 6 -> 13
    {
        int maxtot = BATCH * 4 * 7;
        convt<64,3,2, 64,6,6,13,13,0, false,0><<<dim3(ceil_div(maxtot,TB),4,4), TB>>>(
            zhat, d0w, d0b, nullptr, nullptr, bufC);
        bn_partial<64,169><<<dim3(64,NS_RED), TB>>>(bufC, part);
        bn_final<<<1, 64>>>(part, dbn0g, dbn0b, sc, bi, 64, 1.f/((float)BATCH*169));
    }
    // d1: 64->32, k3 s2 p1, 13 -> 25
    {
        int maxtot = BATCH * 7 * 13;
        convt<64,3,2, 32,13,13,25,25,1, true,0><<<dim3(ceil_div(maxtot,TB),2,4), TB>>>(
            bufC, d1w, d1b, sc, bi, bufB);
        bn_partial<32,625><<<dim3(32,NS_RED), TB>>>(bufB, part);
        bn_final<<<1, 64>>>(part, dbn1g, dbn1b, sc, bi, 32, 1.f/((float)BATCH*625));
    }
    // d2: 32->16, k2 s2 p1 op1, 25 -> 49
    {
        int maxtot = BATCH * 13 * 25;
        convt<32,2,2, 16,25,25,49,49,1, true,0><<<dim3(ceil_div(maxtot,TB),1,4), TB>>>(
            bufB, d2w, d2b, sc, bi, bufA);
        bn_partial<16,2401><<<dim3(16,NS_RED), TB>>>(bufA, part);
        bn_final<<<1, 64>>>(part, dbn2g, dbn2b, sc, bi, 16, 1.f/((float)BATCH*2401));
    }
    // d3: 16->1, k2 s2 p0, 49 -> 98, sigmoid -> out (specialized single-tap)
    {
        int total = BATCH*98*98;
        d3_fast<<<ceil_div(total,TB), TB>>>(bufA, d3w, d3b, sc, bi, out);
    }
}

// round 16
// speedup vs baseline: 1.0424x; 1.0187x over previous
#include <cuda_runtime.h>
#include <math.h>

#define BATCH 512
#define MMEM  2000
#define FDIM  2304
#define NS_RED 64
#define GSPLIT 4

// ---------------- scratch (device globals: allocation-free) ----------------
__device__ float g_bufA[512*16*49*49];
__device__ float g_bufB[512*32*25*25];
__device__ float g_bufC[512*64*13*13];
__device__ float g_t4  [512*2304];
__device__ float g_z   [512*2304];
__device__ float g_zhat[512*2304];
__device__ float g_w   [512*2000];
__device__ float g_zn  [512];
__device__ float g_mn  [2000];
__device__ float g_part[64*NS_RED*2];
__device__ float g_sc  [64];
__device__ float g_bi  [64];
__device__ float g_gpart[8*512*2304];

__device__ __forceinline__ void fma4(float4& a, float4 w, float v) {
    a.x = fmaf(v, w.x, a.x); a.y = fmaf(v, w.y, a.y);
    a.z = fmaf(v, w.z, a.z); a.w = fmaf(v, w.w, a.w);
}

// ======= direct conv, ALL shapes compile-time, incremented pointers ========
template<int CI, int K, int S, int PXY, int CO, int IH, int IW, int OH, int OW,
         int P, bool PRE, int EPI>
__global__ __launch_bounds__(256, 3) void convd(
    const float* __restrict__ in, const float* __restrict__ wgt,
    const float* __restrict__ cbias,
    const float* __restrict__ sc, const float* __restrict__ bi,
    float* __restrict__ out)
{
    constexpr int GY = (OH + PXY - 1) / PXY;
    constexpr int TOTAL = BATCH * GY * OW;
    constexpr int IHW = IH * IW;
    constexpr int OHW = OH * OW;

    __shared__ float wsm[K*K*CI*16];
    __shared__ float scs[CI], bis[CI];
    const int tid = threadIdx.x;
    const int co0 = blockIdx.y * 16;

    constexpr int WN = K*K*CI*16;
    for (int idx = tid; idx < WN; idx += 256) {
        int j = idx & 15, r = idx >> 4;
        int ci = r % CI; r /= CI;
        int kx = r % K, ky = r / K;
        wsm[idx] = wgt[(((co0 + j)*CI + ci)*K + ky)*K + kx];
    }
    if (PRE) for (int c = tid; c < CI; c += 256) { scs[c] = sc[c]; bis[c] = bi[c]; }
    __syncthreads();

    int p = blockIdx.x * 256 + tid;
    if (p >= TOTAL) return;
    const int ox = p % OW; int t = p / OW;
    const int gy = t % GY;
    const int n  = t / GY;
    const int oy0 = gy * PXY;

    float4 acc[PXY][4];
#pragma unroll
    for (int i = 0; i < PXY; i++)
#pragma unroll
        for (int q = 0; q < 4; q++) acc[i][q] = make_float4(0.f,0.f,0.f,0.f);

    const float* inb = in + (long)n * CI * IHW;

#pragma unroll
    for (int ky = 0; ky < K; ky++) {
        int iys[PXY]; bool ym[PXY];
#pragma unroll
        for (int i = 0; i < PXY; i++) {
            int oy = oy0 + i;
            int iy = oy*S - P + ky;
            ym[i] = (oy < OH) && ((unsigned)iy < (unsigned)IH);
            iys[i] = iy;
        }
#pragma unroll
        for (int kx = 0; kx < K; kx++) {
            int ix = ox*S - P + kx;
            bool xm = (unsigned)ix < (unsigned)IW;
            const float* cp[PXY]; bool m[PXY];
#pragma unroll
            for (int i = 0; i < PXY; i++) {
                m[i] = ym[i] && xm;
                cp[i] = inb + iys[i]*IW + ix;
            }
            const float4* wp4 = (const float4*)(wsm + (ky*K + kx)*CI*16);
#pragma unroll 1
            for (int ci0 = 0; ci0 < CI; ci0 += 4) {
                float v[4][PXY];
#pragma unroll
                for (int u = 0; u < 4; u++)
#pragma unroll
                    for (int i = 0; i < PXY; i++)
                        v[u][i] = m[i] ? __ldg(cp[i] + u*IHW) : 0.f;
                if (PRE) {
#pragma unroll
                    for (int u = 0; u < 4; u++) {
                        float scv = scs[ci0+u], biv = bis[ci0+u];
#pragma unroll
                        for (int i = 0; i < PXY; i++)
                            v[u][i] = m[i] ? fmaxf(fmaf(v[u][i], scv, biv), 0.f) : 0.f;
                    }
                }
#pragma unroll
                for (int u = 0; u < 4; u++) {
                    float4 w0 = wp4[u*4+0], w1 = wp4[u*4+1];
                    float4 w2 = wp4[u*4+2], w3 = wp4[u*4+3];
#pragma unroll
                    for (int i = 0; i < PXY; i++) {
                        fma4(acc[i][0], w0, v[u][i]); fma4(acc[i][1], w1, v[u][i]);
                        fma4(acc[i][2], w2, v[u][i]); fma4(acc[i][3], w3, v[u][i]);
                    }
                }
#pragma unroll
                for (int i = 0; i < PXY; i++) cp[i] += 4*IHW;
                wp4 += 16;
            }
        }
    }

    float bv[16];
#pragma unroll
    for (int j = 0; j < 16; j++) bv[j] = __ldg(cbias + co0 + j);
#pragma unroll
    for (int i = 0; i < PXY; i++) {
        int oy = oy0 + i;
        if (oy >= OH) continue;
        long obase = (((long)n*CO + co0)*OH + oy)*OW + ox;
        float r[16];
        r[0]=acc[i][0].x; r[1]=acc[i][0].y; r[2]=acc[i][0].z; r[3]=acc[i][0].w;
        r[4]=acc[i][1].x; r[5]=acc[i][1].y; r[6]=acc[i][1].z; r[7]=acc[i][1].w;
        r[8]=acc[i][2].x; r[9]=acc[i][2].y; r[10]=acc[i][2].z; r[11]=acc[i][2].w;
        r[12]=acc[i][3].x; r[13]=acc[i][3].y; r[14]=acc[i][3].z; r[15]=acc[i][3].w;
#pragma unroll
        for (int j = 0; j < 16; j++) {
            float vv = r[j] + bv[j];
            if (EPI == 1) vv = 1.f / (1.f + expf(-vv));
            out[obase + (long)j*OHW] = vv;
        }
    }
}

// ==== transposed conv (stride 2, parity classes), shapes compile-time ======
template<int CI, int K, int PXY, int CO, int IH, int IW, int OH, int OW,
         int P, bool PRE, int EPI>
__global__ __launch_bounds__(256, 3) void convt(
    const float* __restrict__ in, const float* __restrict__ wgt,
    const float* __restrict__ cbias,
    const float* __restrict__ sc, const float* __restrict__ bi,
    float* __restrict__ out)
{
    constexpr int IHW = IH * IW;
    constexpr int OHW = OH * OW;

    __shared__ float wsm[K*K*CI*16];
    __shared__ float scs[CI], bis[CI];
    const int tid = threadIdx.x;
    const int co0 = blockIdx.y * 16;

    constexpr int WN = K*K*CI*16;
    for (int idx = tid; idx < WN; idx += 256) {
        int j = idx & 15, r = idx >> 4;
        int ci = r % CI; r /= CI;
        int kx = r % K, ky = r / K;
        wsm[idx] = wgt[((ci*CO + co0 + j)*K + ky)*K + kx];  // (in,out,kh,kw)
    }
    if (PRE) for (int c = tid; c < CI; c += 256) { scs[c] = sc[c]; bis[c] = bi[c]; }
    __syncthreads();

    const int pyc = blockIdx.z >> 1;
    const int pxc = blockIdx.z & 1;
    const int OHc = (OH - pyc + 1) >> 1;
    const int OWc = (OW - pxc + 1) >> 1;
    const int GYc = (OHc + PXY - 1) / PXY;
    const int totalc = BATCH * GYc * OWc;

    int p = blockIdx.x * 256 + tid;
    if (p >= totalc) return;
    const int jx = p % OWc; int t = p / OWc;
    const int gy = t % GYc;
    const int n  = t / GYc;
    const int jy0 = gy * PXY;
    const int ox = pxc + 2*jx;

    float4 acc[PXY][4];
#pragma unroll
    for (int i = 0; i < PXY; i++)
#pragma unroll
        for (int q = 0; q < 4; q++) acc[i][q] = make_float4(0.f,0.f,0.f,0.f);

    const float* inb = in + (long)n * CI * IHW;

#pragma unroll
    for (int ky = 0; ky < K; ky++) {
        int dy = pyc + P - ky;
        if (dy & 1) continue;
        int iy0 = (dy >> 1) + jy0;
        bool ym[PXY]; int iys[PXY];
#pragma unroll
        for (int i = 0; i < PXY; i++) {
            int iy = iy0 + i;
            ym[i] = ((jy0 + i) < OHc) && ((unsigned)iy < (unsigned)IH);
            iys[i] = iy;
        }
#pragma unroll
        for (int kx = 0; kx < K; kx++) {
            int dx = pxc + P - kx;
            if (dx & 1) continue;
            int ix = (dx >> 1) + jx;
            bool xm = (unsigned)ix < (unsigned)IW;
            const float* cp[PXY]; bool m[PXY];
#pragma unroll
            for (int i = 0; i < PXY; i++) {
                m[i] = ym[i] && xm;
                cp[i] = inb + iys[i]*IW + ix;
            }
            const float4* wp4 = (const float4*)(wsm + (ky*K + kx)*CI*16);
#pragma unroll 1
            for (int ci0 = 0; ci0 < CI; ci0 += 4) {
                float v[4][PXY];
#pragma unroll
                for (int u = 0; u < 4; u++)
#pragma unroll
                    for (int i = 0; i < PXY; i++)
                        v[u][i] = m[i] ? __ldg(cp[i] + u*IHW) : 0.f;
                if (PRE) {
#pragma unroll
                    for (int u = 0; u < 4; u++) {
                        float scv = scs[ci0+u], biv = bis[ci0+u];
#pragma unroll
                        for (int i = 0; i < PXY; i++)
                            v[u][i] = m[i] ? fmaxf(fmaf(v[u][i], scv, biv), 0.f) : 0.f;
                    }
                }
#pragma unroll
                for (int u = 0; u < 4; u++) {
                    float4 w0 = wp4[u*4+0], w1 = wp4[u*4+1];
                    float4 w2 = wp4[u*4+2], w3 = wp4[u*4+3];
#pragma unroll
                    for (int i = 0; i < PXY; i++) {
                        fma4(acc[i][0], w0, v[u][i]); fma4(acc[i][1], w1, v[u][i]);
                        fma4(acc[i][2], w2, v[u][i]); fma4(acc[i][3], w3, v[u][i]);
                    }
                }
#pragma unroll
                for (int i = 0; i < PXY; i++) cp[i] += 4*IHW;
                wp4 += 16;
            }
        }
    }

    float bvv[16];
#pragma unroll
    for (int j = 0; j < 16; j++) bvv[j] = __ldg(cbias + co0 + j);
#pragma unroll
    for (int i = 0; i < PXY; i++) {
        if ((jy0 + i) >= OHc) continue;
        int oy = pyc + 2*(jy0 + i);
        long obase = (((long)n*CO + co0)*OH + oy)*OW + ox;
        float r[16];
        r[0]=acc[i][0].x; r[1]=acc[i][0].y; r[2]=acc[i][0].z; r[3]=acc[i][0].w;
        r[4]=acc[i][1].x; r[5]=acc[i][1].y; r[6]=acc[i][1].z; r[7]=acc[i][1].w;
        r[8]=acc[i][2].x; r[9]=acc[i][2].y; r[10]=acc[i][2].z; r[11]=acc[i][2].w;
        r[12]=acc[i][3].x; r[13]=acc[i][3].y; r[14]=acc[i][3].z; r[15]=acc[i][3].w;
#pragma unroll
        for (int j = 0; j < 16; j++) {
            float vv = r[j] + bvv[j];
            if (EPI == 1) vv = 1.f / (1.f + expf(-vv));
            out[obase + (long)j*OHW] = vv;
        }
    }
}

// ================= specialized conv1: 1->16, k1 s2 p1, 96->49 ===============
__global__ __launch_bounds__(256) void conv1_fast(
    const float* __restrict__ x, const float* __restrict__ wgt,
    const float* __restrict__ cbias, float* __restrict__ out)
{
    __shared__ float wv[16], bv[16];
    if (threadIdx.x < 16) { wv[threadIdx.x] = wgt[threadIdx.x]; bv[threadIdx.x] = cbias[threadIdx.x]; }
    __syncthreads();

    int p = blockIdx.x * 256 + threadIdx.x;
    const int total = BATCH*49*49;
    if (p >= total) return;
    const int ox = p % 49; int t = p / 49;
    const int oy = t % 49;
    const int n  = t / 49;
    const int iy = 2*oy - 1, ix = 2*ox - 1;
    float v = (iy >= 0 && ix >= 0) ? __ldg(x + ((long)n*96 + iy)*96 + ix) : 0.f;
    long obase = (((long)n*16)*49 + oy)*49 + ox;
#pragma unroll
    for (int co = 0; co < 16; co++)
        out[obase + (long)co*2401] = fmaf(v, wv[co], bv[co]);
}

// ===== specialized d3: 16->1, k2 s2 p0 transposed (single tap) + sigmoid ====
__global__ __launch_bounds__(256) void d3_fast(
    const float* __restrict__ in, const float* __restrict__ wgt,
    const float* __restrict__ cbias,
    const float* __restrict__ sc, const float* __restrict__ bi,
    float* __restrict__ out)
{
    __shared__ float wsm[64];
    __shared__ float scs[16], bis[16];
    if (threadIdx.x < 64) wsm[threadIdx.x] = wgt[threadIdx.x];
    if (threadIdx.x < 16) { scs[threadIdx.x] = sc[threadIdx.x]; bis[threadIdx.x] = bi[threadIdx.x]; }
    __syncthreads();

    int p = blockIdx.x * 256 + threadIdx.x;
    const int total = BATCH*98*98;
    if (p >= total) return;
    const int ox = p % 98; int t = p / 98;
    const int oy = t % 98;
    const int n  = t / 98;
    const int ky = oy & 1, kx = ox & 1;
    const int iy = oy >> 1, ix = ox >> 1;

    const float* inb = in + ((long)n*16*49 + iy)*49 + ix;
    float v[16];
#pragma unroll
    for (int ci = 0; ci < 16; ci++) v[ci] = __ldg(inb + ci*2401);
    float s = __ldg(cbias);
    const int wo = ky*2 + kx;
#pragma unroll
    for (int ci = 0; ci < 16; ci++) {
        float r = fmaxf(fmaf(v[ci], scs[ci], bis[ci]), 0.f);
        s = fmaf(r, wsm[ci*4 + wo], s);
    }
    out[((long)n*98 + oy)*98 + ox] = 1.f / (1.f + expf(-s));
}

// ---- BN statistics (flat index, MLP-4 unrolled, deterministic) ------------
template<int C, int HW>
__global__ void bn_partial(const float* __restrict__ in, float* __restrict__ part)
{
    const int c  = blockIdx.x;
    const int sb = blockIdx.y;
    constexpr long TOT = (long)BATCH * HW;
    const long stride = 256L * NS_RED;
    float s = 0.f, q = 0.f;
#pragma unroll 4
    for (long e = (long)sb*256 + threadIdx.x; e < TOT; e += stride) {
        int n = (int)(e / HW), i = (int)(e % HW);
        float v = __ldg(in + ((long)n*C + c)*HW + i);
        s += v; q += v*v;
    }
    __shared__ float rs[256], rq[256];
    int tid = threadIdx.x;
    rs[tid] = s; rq[tid] = q; __syncthreads();
    for (int o = 128; o > 0; o >>= 1) {
        if (tid < o) { rs[tid] += rs[tid+o]; rq[tid] += rq[tid+o]; }
        __syncthreads();
    }
    if (tid == 0) { part[(c*NS_RED + sb)*2] = rs[0]; part[(c*NS_RED + sb)*2 + 1] = rq[0]; }
}

__global__ void bn_final(const float* __restrict__ part, const float* __restrict__ g,
                         const float* __restrict__ b, float* __restrict__ sc,
                         float* __restrict__ bi, int C, float invN)
{
    int c = blockIdx.x * blockDim.x + threadIdx.x;
    if (c >= C) return;
    float s = 0.f, q = 0.f;
    for (int k = 0; k < NS_RED; k++) { s += part[(c*NS_RED+k)*2]; q += part[(c*NS_RED+k)*2+1]; }
    float m   = s * invN;
    float var = fmaxf(q * invN - m*m, 0.f);
    float scale = g[c] * rsqrtf(var + 1e-5f);
    sc[c] = scale;
    bi[c] = b[c] - m * scale;
}

// ======= fused: z = relu(bn4(t4)) + row L2 norm (one block per row) ========
__global__ void zprep(const float* __restrict__ t4, const float* __restrict__ sc,
                      const float* __restrict__ bi, float* __restrict__ z,
                      float* __restrict__ zn)
{
    const int n = blockIdx.x, tid = threadIdx.x;
    const float* trow = t4 + (long)n * FDIM;
    float* zrow = z + (long)n * FDIM;
    float s = 0.f;
    for (int i = tid; i < FDIM; i += 256) {
        int c = i / 36;
        float v = fmaxf(fmaf(trow[i], sc[c], bi[c]), 0.f);
        zrow[i] = v;
        s += v*v;
    }
    __shared__ float rs[256];
    rs[tid] = s; __syncthreads();
    for (int o = 128; o > 0; o >>= 1) {
        if (tid < o) rs[tid] += rs[tid+o];
        __syncthreads();
    }
    if (tid == 0) zn[n] = sqrtf(rs[0]);
}

// ---------------- row L2 norm (memory) --------------------------------------
__global__ void rownorm(const float* __restrict__ A, float* __restrict__ out, int cols)
{
    const int r = blockIdx.x;
    const float* row = A + (long)r * cols;
    float s = 0.f;
    for (int i = threadIdx.x; i < cols; i += 256) { float v = row[i]; s += v*v; }
    __shared__ float rs[256];
    rs[threadIdx.x] = s; __syncthreads();
    for (int o = 128; o > 0; o >>= 1) {
        if (threadIdx.x < o) rs[threadIdx.x] += rs[threadIdx.x+o];
        __syncthreads();
    }
    if (threadIdx.x == 0) out[r] = sqrtf(rs[0]);
}

// === 128x128x16 split-K GEMM, register-prefetch double buffer ==============
template<bool BNK, int Mr, int Nr, int Kr>
__global__ __launch_bounds__(256) void gemm128(
    const float* __restrict__ A, const float* __restrict__ Bm,
    float* __restrict__ Cp)
{
    __shared__ float As[16][132];
    __shared__ float Bs[16][132];
    const int tid = threadIdx.x;
    const int row0 = blockIdx.y * 128, col0 = blockIdx.x * 128;
    constexpr int CHUNK = ((Kr/16 + GSPLIT - 1)/GSPLIT)*16;
    const int kb = blockIdx.z * CHUNK;
    const int ke = (Kr < kb + CHUNK) ? Kr : (kb + CHUNK);

    float acc[8][8];
#pragma unroll
    for (int i = 0; i < 8; i++)
#pragma unroll
        for (int j = 0; j < 8; j++) acc[i][j] = 0.f;

    const int lr = tid >> 1;          // row 0..127
    const int lk = (tid & 1) * 8;     // k 0 or 8
    const int bkk = tid >> 4;         // k 0..15 (BNK=false)
    const int bj  = (tid & 15) * 8;   // col 0..120
    const int ty = tid >> 4, tx = tid & 15;

    float4 pa0, pa1, pb0, pb1;
    // prefetch first tile
    {
        const float* ap = A + (long)(row0 + lr)*Kr + kb + lk;
        pa0 = *(const float4*)ap; pa1 = *(const float4*)(ap + 4);
        if (BNK) {
            int gc = col0 + lr;
            pb0 = make_float4(0.f,0.f,0.f,0.f); pb1 = pb0;
            if (gc < Nr) {
                const float* bp = Bm + (long)gc*Kr + kb + lk;
                pb0 = *(const float4*)bp; pb1 = *(const float4*)(bp + 4);
            }
        } else {
            const float* bp = Bm + (long)(kb + bkk)*Nr + col0 + bj;
            pb0 = *(const float4*)bp; pb1 = *(const float4*)(bp + 4);
        }
    }

    for (int k0 = kb; k0 < ke; k0 += 16) {
        // stage regs -> smem
        As[lk+0][lr]=pa0.x; As[lk+1][lr]=pa0.y; As[lk+2][lr]=pa0.z; As[lk+3][lr]=pa0.w;
        As[lk+4][lr]=pa1.x; As[lk+5][lr]=pa1.y; As[lk+6][lr]=pa1.z; As[lk+7][lr]=pa1.w;
        if (BNK) {
            Bs[lk+0][lr]=pb0.x; Bs[lk+1][lr]=pb0.y; Bs[lk+2][lr]=pb0.z; Bs[lk+3][lr]=pb0.w;
            Bs[lk+4][lr]=pb1.x; Bs[lk+5][lr]=pb1.y; Bs[lk+6][lr]=pb1.z; Bs[lk+7][lr]=pb1.w;
        } else {
            *(float4*)&Bs[bkk][bj]   = pb0;
            *(float4*)&Bs[bkk][bj+4] = pb1;
        }
        __syncthreads();

        // prefetch next tile while computing this one
        if (k0 + 16 < ke) {
            const float* ap = A + (long)(row0 + lr)*Kr + (k0+16) + lk;
            pa0 = *(const float4*)ap; pa1 = *(const float4*)(ap + 4);
            if (BNK) {
                int gc = col0 + lr;
                pb0 = make_float4(0.f,0.f,0.f,0.f); pb1 = pb0;
                if (gc < Nr) {
                    const float* bp = Bm + (long)gc*Kr + (k0+16) + lk;
                    pb0 = *(const float4*)bp; pb1 = *(const float4*)(bp + 4);
                }
            } else {
                const float* bp = Bm + (long)((k0+16) + bkk)*Nr + col0 + bj;
                pb0 = *(const float4*)bp; pb1 = *(const float4*)(bp + 4);
            }
        }

#pragma unroll
        for (int kk = 0; kk < 16; kk++) {
            float4 a0 = *(const float4*)&As[kk][ty*4];
            float4 a1 = *(const float4*)&As[kk][64 + ty*4];
            float4 b0 = *(const float4*)&Bs[kk][tx*4];
            float4 b1 = *(const float4*)&Bs[kk][64 + tx*4];
            float a[8] = {a0.x,a0.y,a0.z,a0.w,a1.x,a1.y,a1.z,a1.w};
            float b[8] = {b0.x,b0.y,b0.z,b0.w,b1.x,b1.y,b1.z,b1.w};
#pragma unroll
            for (int i = 0; i < 8; i++)
#pragma unroll
                for (int j = 0; j < 8; j++) acc[i][j] = fmaf(a[i], b[j], acc[i][j]);
        }
        __syncthreads();
    }

    const long zoff = (long)blockIdx.z * Mr * Nr;
#pragma unroll
    for (int i = 0; i < 8; i++) {
        int gr = row0 + ((i < 4) ? (ty*4 + i) : (64 + ty*4 + i - 4));
        int gc0 = col0 + tx*4;
        int gc1 = col0 + 64 + tx*4;
        float4 s0 = make_float4(acc[i][0], acc[i][1], acc[i][2], acc[i][3]);
        float4 s1 = make_float4(acc[i][4], acc[i][5], acc[i][6], acc[i][7]);
        if (gc0 < Nr) *(float4*)&Cp[zoff + (long)gr*Nr + gc0] = s0;
        if (gc1 < Nr) *(float4*)&Cp[zoff + (long)gr*Nr + gc1] = s1;
    }
}

__global__ void kreduce0(const float* __restrict__ part, float* __restrict__ outp,
                         int Mr, int Nr)
{
    int i = blockIdx.x * blockDim.x + threadIdx.x;
    if (i >= Mr*Nr) return;
    const long stride = (long)Mr * Nr;
    float s = 0.f;
#pragma unroll
    for (int k = 0; k < GSPLIT; k++) s += part[k*stride + i];
    outp[i] = s;
}

// ==== fused: split-K sum + cosine + softmax + hard-shrink + L1 renorm =======
__global__ void addr_fused(const float* __restrict__ gpart, float* __restrict__ w,
                           const float* __restrict__ zn, const float* __restrict__ mn)
{
    __shared__ float srow[MMEM];
    __shared__ float red[256];
    const int n = blockIdx.x, tid = threadIdx.x;
    const long stride = (long)BATCH * MMEM;
    const float zv = zn[n];

    float mx = -1e30f;
    for (int i = tid; i < MMEM; i += 256) {
        long base = (long)n * MMEM + i;
        float s = 0.f;
#pragma unroll
        for (int k = 0; k < GSPLIT; k++) s += gpart[k*stride + base];
        s = s / fmaxf(zv * mn[i], 1e-8f);
        srow[i] = s; mx = fmaxf(mx, s);
    }
    red[tid] = mx; __syncthreads();
    for (int o = 128; o > 0; o >>= 1) { if (tid < o) red[tid] = fmaxf(red[tid], red[tid+o]); __syncthreads(); }
    mx = red[0]; __syncthreads();

    float s = 0.f;
    for (int i = tid; i < MMEM; i += 256) { float e = expf(srow[i] - mx); srow[i] = e; s += e; }
    red[tid] = s; __syncthreads();
    for (int o = 128; o > 0; o >>= 1) { if (tid < o) red[tid] += red[tid+o]; __syncthreads(); }
    float inv = 1.f / red[0]; __syncthreads();

    const float t = 1.f / 2000.f;
    float s2 = 0.f;
    for (int i = tid; i < MMEM; i += 256) {
        float wv = srow[i] * inv;
        float u  = wv - t;
        float sh = (u > 0.f) ? (u * wv / (u + 0.01f)) : 0.f;
        srow[i] = sh; s2 += sh;
    }
    red[tid] = s2; __syncthreads();
    for (int o = 128; o > 0; o >>= 1) { if (tid < o) red[tid] += red[tid+o]; __syncthreads(); }
    float inv2 = 1.f / red[0]; __syncthreads();

    float* row = w + (long)n * MMEM;
    for (int i = tid; i < MMEM; i += 256) row[i] = srow[i] * inv2;
}

// ---------------------------------------------------------------------------
static inline int ceil_div(int a, int b) { return (a + b - 1) / b; }

extern "C" void kernel_launch(void* const* d_in, const int* in_sizes, int n_in,
                              void* d_out, int out_size)
{
    const float* x     = (const float*)d_in[0];
    const float* c1w   = (const float*)d_in[1];  const float* c1b  = (const float*)d_in[2];
    const float* bn1g  = (const float*)d_in[3];  const float* bn1b = (const float*)d_in[4];
    const float* c2w   = (const float*)d_in[5];  const float* c2b  = (const float*)d_in[6];
    const float* bn2g  = (const float*)d_in[7];  const float* bn2b = (const float*)d_in[8];
    const float* c3w   = (const float*)d_in[9];  const float* c3b  = (const float*)d_in[10];
    const float* bn3g  = (const float*)d_in[11]; const float* bn3b = (const float*)d_in[12];
    const float* c4w   = (const float*)d_in[13]; const float* c4b  = (const float*)d_in[14];
    const float* bn4g  = (const float*)d_in[15]; const float* bn4b = (const float*)d_in[16];
    const float* mem   = (const float*)d_in[17];
    const float* d0w   = (const float*)d_in[18]; const float* d0b  = (const float*)d_in[19];
    const float* dbn0g = (const float*)d_in[20]; const float* dbn0b= (const float*)d_in[21];
    const float* d1w   = (const float*)d_in[22]; const float* d1b  = (const float*)d_in[23];
    const float* dbn1g = (const float*)d_in[24]; const float* dbn1b= (const float*)d_in[25];
    const float* d2w   = (const float*)d_in[26]; const float* d2b  = (const float*)d_in[27];
    const float* dbn2g = (const float*)d_in[28]; const float* dbn2b= (const float*)d_in[29];
    const float* d3w   = (const float*)d_in[30]; const float* d3b  = (const float*)d_in[31];
    float* out = (float*)d_out;

    float *bufA, *bufB, *bufC, *t4, *z, *zhat, *w, *zn, *mn, *part, *sc, *bi, *gpart;
    cudaGetSymbolAddress((void**)&bufA, g_bufA);
    cudaGetSymbolAddress((void**)&bufB, g_bufB);
    cudaGetSymbolAddress((void**)&bufC, g_bufC);
    cudaGetSymbolAddress((void**)&t4,   g_t4);
    cudaGetSymbolAddress((void**)&z,    g_z);
    cudaGetSymbolAddress((void**)&zhat, g_zhat);
    cudaGetSymbolAddress((void**)&w,    g_w);
    cudaGetSymbolAddress((void**)&zn,   g_zn);
    cudaGetSymbolAddress((void**)&mn,   g_mn);
    cudaGetSymbolAddress((void**)&part, g_part);
    cudaGetSymbolAddress((void**)&sc,   g_sc);
    cudaGetSymbolAddress((void**)&bi,   g_bi);
    cudaGetSymbolAddress((void**)&gpart, g_gpart);

    const int TB = 256;

    // ---- encoder ----
    // conv1: 1->16, k1 s2 p1, 96 -> 49 (specialized)
    {
        int total = BATCH*49*49;
        conv1_fast<<<ceil_div(total,TB), TB>>>(x, c1w, c1b, bufA);
        bn_partial<16,2401><<<dim3(16,NS_RED), TB>>>(bufA, part);
        bn_final<<<1, 64>>>(part, bn1g, bn1b, sc, bi, 16, 1.f/((float)BATCH*2401));
    }
    // conv2: 16->32, k3 s2 p1, 49 -> 25
    {
        int total = BATCH*13*25;
        convd<16,3,2,2, 32,49,49,25,25,1, true,0><<<dim3(ceil_div(total,TB),2), TB>>>(
            bufA, c2w, c2b, sc, bi, bufB);
        bn_partial<32,625><<<dim3(32,NS_RED), TB>>>(bufB, part);
        bn_final<<<1, 64>>>(part, bn2g, bn2b, sc, bi, 32, 1.f/((float)BATCH*625));
    }
    // conv3: 32->64, k3 s2 p1, 25 -> 13
    {
        int total = BATCH*7*13;
        convd<32,3,2,2, 64,25,25,13,13,1, true,0><<<dim3(ceil_div(total,TB),4), TB>>>(
            bufB, c3w, c3b, sc, bi, bufC);
        bn_partial<64,169><<<dim3(64,NS_RED), TB>>>(bufC, part);
        bn_final<<<1, 64>>>(part, bn3g, bn3b, sc, bi, 64, 1.f/((float)BATCH*169));
    }
    // conv4: 64->64, k3 s2 p0, 13 -> 6
    {
        int total = BATCH*3*6;
        convd<64,3,2,2, 64,13,13,6,6,0, true,0><<<dim3(ceil_div(total,TB),4), TB>>>(
            bufC, c4w, c4b, sc, bi, t4);
        bn_partial<64,36><<<dim3(64,NS_RED), TB>>>(t4, part);
        bn_final<<<1, 64>>>(part, bn4g, bn4b, sc, bi, 64, 1.f/((float)BATCH*36));
    }

    // ---- memory addressing ----
    {
        zprep<<<BATCH, 256>>>(t4, sc, bi, z, zn);
        rownorm<<<MMEM, 256>>>(mem, mn, FDIM);
        gemm128<true, BATCH, MMEM, FDIM><<<dim3(ceil_div(MMEM,128), BATCH/128, GSPLIT), 256>>>(
            z, mem, gpart);
        addr_fused<<<BATCH, 256>>>(gpart, w, zn, mn);
        gemm128<false, BATCH, FDIM, MMEM><<<dim3(FDIM/128, BATCH/128, GSPLIT), 256>>>(
            w, mem, gpart);
        kreduce0<<<ceil_div(BATCH*FDIM,TB), TB>>>(gpart, zhat, BATCH, FDIM);
    }

    // ---- decoder ----
    // d0: 64->64, k3 s2 p0, 6 -> 13
    {
        int maxtot = BATCH * 4 * 7;
        convt<64,3,2, 64,6,6,13,13,0, false,0><<<dim3(ceil_div(maxtot,TB),4,4), TB>>>(
            zhat, d0w, d0b, nullptr, nullptr, bufC);
        bn_partial<64,169><<<dim3(64,NS_RED), TB>>>(bufC, part);
        bn_final<<<1, 64>>>(part, dbn0g, dbn0b, sc, bi, 64, 1.f/((float)BATCH*169));
    }
    // d1: 64->32, k3 s2 p1, 13 -> 25
    {
        int maxtot = BATCH * 7 * 13;
        convt<64,3,2, 32,13,13,25,25,1, true,0><<<dim3(ceil_div(maxtot,TB),2,4), TB>>>(
            bufC, d1w, d1b, sc, bi, bufB);
        bn_partial<32,625><<<dim3(32,NS_RED), TB>>>(bufB, part);
        bn_final<<<1, 64>>>(part, dbn1g, dbn1b, sc, bi, 32, 1.f/((float)BATCH*625));
    }
    // d2: 32->16, k2 s2 p1 op1, 25 -> 49
    {
        int maxtot = BATCH * 13 * 25;
        convt<32,2,2, 16,25,25,49,49,1, true,0><<<dim3(ceil_div(maxtot,TB),1,4), TB>>>(
            bufB, d2w, d2b, sc, bi, bufA);
        bn_partial<16,2401><<<dim3(16,NS_RED), TB>>>(bufA, part);
        bn_final<<<1, 64>>>(part, dbn2g, dbn2b, sc, bi, 16, 1.f/((float)BATCH*2401));
    }
    // d3: 16->1, k2 s2 p0, 49 -> 98, sigmoid -> out (specialized single-tap)
    {
        int total = BATCH*98*98;
        d3_fast<<<ceil_div(total,TB), TB>>>(bufA, d3w, d3b, sc, bi, out);
    }
}